// round 7
// baseline (speedup 1.0000x reference)
#include <cuda_runtime.h>
#include <cstdint>

#define NN 512000       // nodes = 512 * 1000
#define NE 8192000      // edges per branch
#define NB 512          // batch
#define NS 1000         // stations
#define NH 64           // ff hidden
#define NA 1024         // actions
#define EPSF 1e-5f

#define TB 256
#define GN 2000                 // 2000 * 256 = NN exactly
#define STATS_BLKS 1024
#define EDGE_BLKS8 4000         // 4000 * 256 * 8 = NE exactly

// ---------------- scratch ----------------------------------------------------
__device__ float    g_stats[3][16];        // per branch: sum[8], sumsq[8]
__device__ unsigned g_deg[3][NN];          // edge-count per dst (no self loop)
__device__ float4   g_z1[3][NN];           // xw * dinv
__device__ float4   g_acc1[3][NN];         // conv1 accumulator (init = self loop)
__device__ float    g_z2[3][NN];
__device__ float    g_acc2[3][NN];

// ---------------- device helpers (all compile-time branch/phase) --------------

// edge phases: 0 = deg histogram, 1 = conv1 scatter, 2 = conv2 scatter
template <int P, int BR>
__device__ __forceinline__ void edgeWork(const int* __restrict__ ei, int blk,
                                         int tid) {
    int base = blk * 2048 + tid * 8;
    if (P == 0) {
        int4 a = __ldcs((const int4*)(ei + NE + base));
        int4 b = __ldcs((const int4*)(ei + NE + base + 4));
        atomicAdd(&g_deg[BR][a.x], 1u);
        atomicAdd(&g_deg[BR][a.y], 1u);
        atomicAdd(&g_deg[BR][a.z], 1u);
        atomicAdd(&g_deg[BR][a.w], 1u);
        atomicAdd(&g_deg[BR][b.x], 1u);
        atomicAdd(&g_deg[BR][b.y], 1u);
        atomicAdd(&g_deg[BR][b.z], 1u);
        atomicAdd(&g_deg[BR][b.w], 1u);
    } else if (P == 1) {
        int4 sa = __ldcs((const int4*)(ei + base));
        int4 sb = __ldcs((const int4*)(ei + base + 4));
        int4 da = __ldcs((const int4*)(ei + NE + base));
        int4 db = __ldcs((const int4*)(ei + NE + base + 4));
        float4 z0 = __ldg(&g_z1[BR][sa.x]);
        float4 z1 = __ldg(&g_z1[BR][sa.y]);
        float4 z2 = __ldg(&g_z1[BR][sa.z]);
        float4 z3 = __ldg(&g_z1[BR][sa.w]);
        float4 z4 = __ldg(&g_z1[BR][sb.x]);
        float4 z5 = __ldg(&g_z1[BR][sb.y]);
        float4 z6 = __ldg(&g_z1[BR][sb.z]);
        float4 z7 = __ldg(&g_z1[BR][sb.w]);
        atomicAdd(&g_acc1[BR][da.x], z0);
        atomicAdd(&g_acc1[BR][da.y], z1);
        atomicAdd(&g_acc1[BR][da.z], z2);
        atomicAdd(&g_acc1[BR][da.w], z3);
        atomicAdd(&g_acc1[BR][db.x], z4);
        atomicAdd(&g_acc1[BR][db.y], z5);
        atomicAdd(&g_acc1[BR][db.z], z6);
        atomicAdd(&g_acc1[BR][db.w], z7);
    } else {
        int4 sa = __ldcs((const int4*)(ei + base));
        int4 sb = __ldcs((const int4*)(ei + base + 4));
        int4 da = __ldcs((const int4*)(ei + NE + base));
        int4 db = __ldcs((const int4*)(ei + NE + base + 4));
        float v0 = __ldg(&g_z2[BR][sa.x]);
        float v1 = __ldg(&g_z2[BR][sa.y]);
        float v2 = __ldg(&g_z2[BR][sa.z]);
        float v3 = __ldg(&g_z2[BR][sa.w]);
        float v4 = __ldg(&g_z2[BR][sb.x]);
        float v5 = __ldg(&g_z2[BR][sb.y]);
        float v6 = __ldg(&g_z2[BR][sb.z]);
        float v7 = __ldg(&g_z2[BR][sb.w]);
        atomicAdd(&g_acc2[BR][da.x], v0);
        atomicAdd(&g_acc2[BR][da.y], v1);
        atomicAdd(&g_acc2[BR][da.z], v2);
        atomicAdd(&g_acc2[BR][da.w], v3);
        atomicAdd(&g_acc2[BR][db.x], v4);
        atomicAdd(&g_acc2[BR][db.y], v5);
        atomicAdd(&g_acc2[BR][db.z], v6);
        atomicAdd(&g_acc2[BR][db.w], v7);
    }
}

// node phase 0: z1 = (norm(x)@W1)*dinv, GraphNorm affine folded into W1
template <int BR>
__device__ __forceinline__ void nodeZ1(const float* __restrict__ x,
                                       const float* __restrict__ nw,
                                       const float* __restrict__ nbp,
                                       const float* __restrict__ nms,
                                       const float* __restrict__ W1,
                                       int blk, int tid) {
    __shared__ float sA[32];
    __shared__ float sD[4];
    if (tid == 0) {
        const float inv = 1.0f / (float)NN;
        float a[8], d[8];
#pragma unroll
        for (int i = 0; i < 8; i++) {
            float mean = g_stats[BR][i] * inv;
            float m2   = g_stats[BR][8 + i] * inv;
            float c    = mean * nms[i];
            float var  = m2 - 2.f * c * mean + c * c;
            float ai   = nw[i] * rsqrtf(var + EPSF);
            a[i] = ai;
            d[i] = nbp[i] - c * ai;
        }
#pragma unroll
        for (int j = 0; j < 4; j++) {
            float dv = 0.f;
#pragma unroll
            for (int i = 0; i < 8; i++) {
                sA[i * 4 + j] = a[i] * W1[i * 4 + j];
                dv += d[i] * W1[i * 4 + j];
            }
            sD[j] = dv;
        }
    }
    __syncthreads();
    int n = blk * TB + tid;
    const float4* p = (const float4*)(x + (size_t)n * 8);
    float4 a = __ldg(p), b = __ldg(p + 1);
    float v[8] = {a.x, a.y, a.z, a.w, b.x, b.y, b.z, b.w};
    float dinv = rsqrtf((float)(g_deg[BR][n] + 1u));
    float o[4];
#pragma unroll
    for (int j = 0; j < 4; j++) {
        float acc = sD[j];
#pragma unroll
        for (int i = 0; i < 8; i++) acc += v[i] * sA[i * 4 + j];
        o[j] = acc * dinv;
    }
    float4 z = make_float4(o[0], o[1], o[2], o[3]);
    g_z1[BR][n]  = z;
    g_acc1[BR][n] = z;
}

// node phase 1: h1 = relu(dinv*acc1+b1); z2 = (h1.w2)*dinv; acc2 init = z2
template <int BR>
__device__ __forceinline__ void nodeH1Z2(const float* __restrict__ b1,
                                         const float* __restrict__ w2,
                                         int blk, int tid) {
    int n = blk * TB + tid;
    float dinv = rsqrtf((float)(g_deg[BR][n] + 1u));
    float4 acc = g_acc1[BR][n];
    float h0 = fmaxf(fmaf(dinv, acc.x, b1[0]), 0.f);
    float h1 = fmaxf(fmaf(dinv, acc.y, b1[1]), 0.f);
    float h2 = fmaxf(fmaf(dinv, acc.z, b1[2]), 0.f);
    float h3 = fmaxf(fmaf(dinv, acc.w, b1[3]), 0.f);
    float z2 = (h0 * w2[0] + h1 * w2[1] + h2 * w2[2] + h3 * w2[3]) * dinv;
    g_z2[BR][n]  = z2;
    g_acc2[BR][n] = z2;
}

// ---------------- kernels ----------------------------------------------------

__global__ void zeroK() {
    int i = blockIdx.x * blockDim.x + threadIdx.x;
    if (i < 3 * NN) ((unsigned*)g_deg)[i] = 0u;
    if (i < 48)     ((float*)g_stats)[i] = 0.f;
}

// stats for all 3 branches + deg histogram for branch 0
__global__ void statsAllDeg0K(const float* __restrict__ x0,
                              const float* __restrict__ x1,
                              const float* __restrict__ x2,
                              const int* __restrict__ e0) {
    if (blockIdx.x < 3 * STATS_BLKS) {
        int br  = blockIdx.x / STATS_BLKS;
        int blk = blockIdx.x - br * STATS_BLKS;
        const float* x = br == 0 ? x0 : (br == 1 ? x1 : x2);
        float s[8], q[8];
#pragma unroll
        for (int i = 0; i < 8; i++) { s[i] = 0.f; q[i] = 0.f; }
        int stride = STATS_BLKS * TB;
        for (int n = blk * TB + threadIdx.x; n < NN; n += stride) {
            const float4* p = (const float4*)(x + (size_t)n * 8);
            float4 a = __ldg(p), b = __ldg(p + 1);
            float v[8] = {a.x, a.y, a.z, a.w, b.x, b.y, b.z, b.w};
#pragma unroll
            for (int i = 0; i < 8; i++) { s[i] += v[i]; q[i] += v[i] * v[i]; }
        }
#pragma unroll
        for (int i = 0; i < 8; i++) {
#pragma unroll
            for (int o = 16; o; o >>= 1) {
                s[i] += __shfl_down_sync(0xffffffffu, s[i], o);
                q[i] += __shfl_down_sync(0xffffffffu, q[i], o);
            }
        }
        __shared__ float sh[16];
        if (threadIdx.x < 16) sh[threadIdx.x] = 0.f;
        __syncthreads();
        if ((threadIdx.x & 31) == 0) {
#pragma unroll
            for (int i = 0; i < 8; i++) {
                atomicAdd(&sh[i], s[i]);
                atomicAdd(&sh[8 + i], q[i]);
            }
        }
        __syncthreads();
        if (threadIdx.x < 16) atomicAdd(&g_stats[br][threadIdx.x], sh[threadIdx.x]);
    } else {
        edgeWork<0, 0>(e0, blockIdx.x - 3 * STATS_BLKS, threadIdx.x);
    }
}

// pipelined stage: 1-2 edge jobs + 0-2 node jobs, all compile-time selected.
// Negative phase = job absent (dead-code eliminated).
template <int E0P, int E0B, int E1P, int E1B, int N0P, int N0B, int N1P, int N1B>
__global__ void stageK(const int* __restrict__ ea, const int* __restrict__ eb,
                       const float* __restrict__ xa, const float* __restrict__ xb,
                       const float* __restrict__ nw, const float* __restrict__ nbp,
                       const float* __restrict__ nms, const float* __restrict__ W1,
                       const float* __restrict__ b1, const float* __restrict__ w2) {
    int bx = blockIdx.x;
    if (bx < EDGE_BLKS8) {
        edgeWork<(E0P < 0 ? 0 : E0P), E0B>(ea, bx, threadIdx.x);
        return;
    }
    bx -= EDGE_BLKS8;
    if (E1P >= 0) {
        if (bx < EDGE_BLKS8) {
            edgeWork<(E1P < 0 ? 0 : E1P), E1B>(eb, bx, threadIdx.x);
            return;
        }
        bx -= EDGE_BLKS8;
    }
    if (N0P >= 0) {
        if (bx < GN) {
            if (N0P == 0) nodeZ1<N0B>(xa, nw, nbp, nms, W1, bx, threadIdx.x);
            else          nodeH1Z2<N0B>(b1, w2, bx, threadIdx.x);
            return;
        }
        bx -= GN;
    }
    if (N1P >= 0) {
        if (N1P == 0) nodeZ1<N1B>(xb, nw, nbp, nms, W1, bx, threadIdx.x);
        else          nodeH1Z2<N1B>(b1, w2, bx, threadIdx.x);
    }
}

// fused conv2 epilogue + concat + ff1 + ff2 + mask
__global__ void ffK(const float* __restrict__ b2, const float* __restrict__ w1f,
                    const float* __restrict__ b1f, const float* __restrict__ w2f,
                    const float* __restrict__ b2f, const float* __restrict__ mask,
                    float* __restrict__ out) {
    __shared__ float row[3 * NS];
    __shared__ float part[4][NH];
    __shared__ float hid[NH];
    int b = blockIdx.x;
    for (int k = threadIdx.x; k < 3 * NS; k += TB) {
        int br = k / NS;
        int s  = k - br * NS;
        int n  = b * NS + s;
        float dinv = rsqrtf((float)(g_deg[br][n] + 1u));
        row[k] = fmaxf(fmaf(dinv, g_acc2[br][n], b2[0]), 0.f);
    }
    __syncthreads();
    int g = threadIdx.x >> 6;
    int j = threadIdx.x & 63;
    float acc = 0.f;
    int k0 = g * 750, k1 = k0 + 750;
    for (int k = k0; k < k1; ++k) acc += row[k] * __ldg(w1f + (size_t)k * NH + j);
    part[g][j] = acc;
    __syncthreads();
    if (threadIdx.x < NH) {
        float v = part[0][threadIdx.x] + part[1][threadIdx.x] +
                  part[2][threadIdx.x] + part[3][threadIdx.x] + b1f[threadIdx.x];
        hid[threadIdx.x] = fmaxf(v, 0.f);
    }
    __syncthreads();
    for (int o = threadIdx.x; o < NA; o += TB) {
        float a2 = b2f[o];
#pragma unroll 8
        for (int k = 0; k < NH; k++) a2 += hid[k] * __ldg(w2f + (size_t)k * NA + o);
        out[(size_t)b * NA + o] = a2 * mask[(size_t)b * NA + o];
    }
}

// ---------------- launch ------------------------------------------------------

extern "C" void kernel_launch(void* const* d_in, const int* in_sizes, int n_in,
                              void* d_out, int out_size) {
    const float* x0 = (const float*)d_in[0];
    const float* x1 = (const float*)d_in[1];
    const float* x2 = (const float*)d_in[2];
    const int* e0 = (const int*)d_in[3];
    const int* e1 = (const int*)d_in[4];
    const int* e2 = (const int*)d_in[5];
    const float* mask = (const float*)d_in[6];
    const float* nw  = (const float*)d_in[7];
    const float* nb  = (const float*)d_in[8];
    const float* nms = (const float*)d_in[9];
    const float* W1  = (const float*)d_in[10];
    const float* b1  = (const float*)d_in[11];
    const float* W2  = (const float*)d_in[12];
    const float* b2  = (const float*)d_in[13];
    const float* wf1 = (const float*)d_in[14];
    const float* bf1 = (const float*)d_in[15];
    const float* wf2 = (const float*)d_in[16];
    const float* bf2 = (const float*)d_in[17];
    float* out = (float*)d_out;

    const int E = EDGE_BLKS8;

    zeroK<<<(3 * NN + TB - 1) / TB, TB>>>();
    // L2: stats(all) + deg(0)
    statsAllDeg0K<<<3 * STATS_BLKS + E, TB>>>(x0, x1, x2, e0);
    // L3: deg(1) + deg(2) + z1(0)
    stageK<0,1, 0,2, 0,0, -1,0><<<2 * E + GN, TB>>>(e1, e2, x0, nullptr,
                                                    nw, nb, nms, W1, b1, W2);
    // L4: scat1(0) + z1(1) + z1(2)
    stageK<1,0, -1,0, 0,1, 0,2><<<E + 2 * GN, TB>>>(e0, nullptr, x1, x2,
                                                    nw, nb, nms, W1, b1, W2);
    // L5: scat1(1) + h1z2(0)
    stageK<1,1, -1,0, 1,0, -1,0><<<E + GN, TB>>>(e1, nullptr, nullptr, nullptr,
                                                 nw, nb, nms, W1, b1, W2);
    // L6: scat1(2) + scat2(0) + h1z2(1)
    stageK<1,2, 2,0, 1,1, -1,0><<<2 * E + GN, TB>>>(e2, e0, nullptr, nullptr,
                                                    nw, nb, nms, W1, b1, W2);
    // L7: scat2(1) + h1z2(2)
    stageK<2,1, -1,0, 1,2, -1,0><<<E + GN, TB>>>(e1, nullptr, nullptr, nullptr,
                                                 nw, nb, nms, W1, b1, W2);
    // L8: scat2(2)
    stageK<2,2, -1,0, -1,0, -1,0><<<E, TB>>>(e2, nullptr, nullptr, nullptr,
                                             nw, nb, nms, W1, b1, W2);
    // L9: fused FF head
    ffK<<<NB, TB>>>(b2, wf1, bf1, wf2, bf2, mask, out);
}

// round 8
// speedup vs baseline: 1.1347x; 1.1347x over previous
#include <cuda_runtime.h>
#include <cstdint>

#define NN 512000       // nodes = 512 * 1000
#define NE 8192000      // edges per branch
#define NB 512          // batch
#define NS 1000         // stations
#define NH 64           // ff hidden
#define NA 1024         // actions
#define EPSF 1e-5f

#define TB 256
#define STATS_BLKS 1024
#define EDGE_BLKS 8000          // 8000 * 256 * 4 = NE exactly
#define KT 40                   // ff1 k-tile (keeps float4 alignment: 40%4==0)

// ---------------- scratch ----------------------------------------------------
__device__ float    g_stats[3][16];        // per branch: sum[8], sumsq[8]
__device__ unsigned g_deg[3][NN];          // edge-count per dst (no self loop)
__device__ float4   g_z1[3][NN];           // xw * dinv
__device__ float4   g_acc1[3][NN];         // conv1 accumulator (init = self loop)
__device__ float    g_z2[3][NN];
__device__ float    g_acc2[3][NN];
__device__ float    g_hidpart[NB * NH];    // ff1 partial sums (k-split)

// ---------------- kernels ----------------------------------------------------

__global__ void zeroK() {
    int i = blockIdx.x * blockDim.x + threadIdx.x;
    if (i < 3 * NN)   ((unsigned*)g_deg)[i] = 0u;
    if (i < 48)       ((float*)g_stats)[i] = 0.f;
    if (i < NB * NH)  g_hidpart[i] = 0.f;
}

// blocks [0,STATS_BLKS) do feature stats, rest do deg histogram. y = branch.
__global__ void statsdegK(const float* __restrict__ x0, const float* __restrict__ x1,
                          const float* __restrict__ x2,
                          const int* __restrict__ e0, const int* __restrict__ e1,
                          const int* __restrict__ e2) {
    int br = blockIdx.y;
    if (blockIdx.x < STATS_BLKS) {
        const float* x = br == 0 ? x0 : (br == 1 ? x1 : x2);
        float s[8], q[8];
#pragma unroll
        for (int i = 0; i < 8; i++) { s[i] = 0.f; q[i] = 0.f; }
        int stride = STATS_BLKS * TB;
        for (int n = blockIdx.x * TB + threadIdx.x; n < NN; n += stride) {
            const float4* p = (const float4*)(x + (size_t)n * 8);
            float4 a = __ldg(p), b = __ldg(p + 1);
            float v[8] = {a.x, a.y, a.z, a.w, b.x, b.y, b.z, b.w};
#pragma unroll
            for (int i = 0; i < 8; i++) { s[i] += v[i]; q[i] += v[i] * v[i]; }
        }
#pragma unroll
        for (int i = 0; i < 8; i++) {
#pragma unroll
            for (int o = 16; o; o >>= 1) {
                s[i] += __shfl_down_sync(0xffffffffu, s[i], o);
                q[i] += __shfl_down_sync(0xffffffffu, q[i], o);
            }
        }
        __shared__ float sh[16];
        if (threadIdx.x < 16) sh[threadIdx.x] = 0.f;
        __syncthreads();
        if ((threadIdx.x & 31) == 0) {
#pragma unroll
            for (int i = 0; i < 8; i++) {
                atomicAdd(&sh[i], s[i]);
                atomicAdd(&sh[8 + i], q[i]);
            }
        }
        __syncthreads();
        if (threadIdx.x < 16) atomicAdd(&g_stats[br][threadIdx.x], sh[threadIdx.x]);
    } else {
        const int* ei = br == 0 ? e0 : (br == 1 ? e1 : e2);
        int base = (blockIdx.x - STATS_BLKS) * 1024 + threadIdx.x * 4;
        int4 d4 = __ldg((const int4*)(ei + NE + base));
        atomicAdd(&g_deg[br][d4.x], 1u);
        atomicAdd(&g_deg[br][d4.y], 1u);
        atomicAdd(&g_deg[br][d4.z], 1u);
        atomicAdd(&g_deg[br][d4.w], 1u);
    }
}

// z1 = (norm(x)@W1)*dinv, GraphNorm affine folded in (thread 0 per block).
__global__ void z1K(const float* __restrict__ x0, const float* __restrict__ x1,
                    const float* __restrict__ x2,
                    const float* __restrict__ nw, const float* __restrict__ nbp,
                    const float* __restrict__ nms, const float* __restrict__ W1) {
    int br = blockIdx.y;
    const float* x = br == 0 ? x0 : (br == 1 ? x1 : x2);
    __shared__ float sA[32];
    __shared__ float sD[4];
    if (threadIdx.x == 0) {
        const float inv = 1.0f / (float)NN;
        float a[8], d[8];
#pragma unroll
        for (int i = 0; i < 8; i++) {
            float mean = g_stats[br][i] * inv;
            float m2   = g_stats[br][8 + i] * inv;
            float c    = mean * nms[i];
            float var  = m2 - 2.f * c * mean + c * c;
            float ai   = nw[i] * rsqrtf(var + EPSF);
            a[i] = ai;
            d[i] = nbp[i] - c * ai;
        }
#pragma unroll
        for (int j = 0; j < 4; j++) {
            float dv = 0.f;
#pragma unroll
            for (int i = 0; i < 8; i++) {
                sA[i * 4 + j] = a[i] * W1[i * 4 + j];
                dv += d[i] * W1[i * 4 + j];
            }
            sD[j] = dv;
        }
    }
    __syncthreads();
    int n = blockIdx.x * TB + threadIdx.x;
    if (n >= NN) return;
    const float4* p = (const float4*)(x + (size_t)n * 8);
    float4 a = __ldg(p), b = __ldg(p + 1);
    float v[8] = {a.x, a.y, a.z, a.w, b.x, b.y, b.z, b.w};
    float dinv = rsqrtf((float)(g_deg[br][n] + 1u));
    float o[4];
#pragma unroll
    for (int j = 0; j < 4; j++) {
        float acc = sD[j];
#pragma unroll
        for (int i = 0; i < 8; i++) acc += v[i] * sA[i * 4 + j];
        o[j] = acc * dinv;
    }
    float4 z = make_float4(o[0], o[1], o[2], o[3]);
    g_z1[br][n]  = z;
    g_acc1[br][n] = z;
}

// conv1 edge scatter, 4 edges/thread: acc1[dst] += z1[src]
__global__ void scat1K(const int* __restrict__ e0, const int* __restrict__ e1,
                       const int* __restrict__ e2) {
    int br = blockIdx.y;
    const int* ei = br == 0 ? e0 : (br == 1 ? e1 : e2);
    int base = blockIdx.x * 1024 + threadIdx.x * 4;
    int4 s4 = __ldg((const int4*)(ei + base));
    int4 d4 = __ldg((const int4*)(ei + NE + base));
    float4 z0 = __ldg(&g_z1[br][s4.x]);
    float4 z1 = __ldg(&g_z1[br][s4.y]);
    float4 z2 = __ldg(&g_z1[br][s4.z]);
    float4 z3 = __ldg(&g_z1[br][s4.w]);
    atomicAdd(&g_acc1[br][d4.x], z0);
    atomicAdd(&g_acc1[br][d4.y], z1);
    atomicAdd(&g_acc1[br][d4.z], z2);
    atomicAdd(&g_acc1[br][d4.w], z3);
}

// h1 = relu(dinv*acc1 + b1); z2 = (h1 . w2) * dinv; acc2 init = z2
__global__ void h1z2K(const float* __restrict__ b1, const float* __restrict__ w2) {
    int br = blockIdx.y;
    int n = blockIdx.x * TB + threadIdx.x;
    if (n >= NN) return;
    float dinv = rsqrtf((float)(g_deg[br][n] + 1u));
    float4 acc = g_acc1[br][n];
    float h0 = fmaxf(fmaf(dinv, acc.x, b1[0]), 0.f);
    float h1 = fmaxf(fmaf(dinv, acc.y, b1[1]), 0.f);
    float h2 = fmaxf(fmaf(dinv, acc.z, b1[2]), 0.f);
    float h3 = fmaxf(fmaf(dinv, acc.w, b1[3]), 0.f);
    float z2 = (h0 * w2[0] + h1 * w2[1] + h2 * w2[2] + h3 * w2[3]) * dinv;
    g_z2[br][n]  = z2;
    g_acc2[br][n] = z2;
}

// conv2 edge scatter, 4 edges/thread: acc2[dst] += z2[src]
__global__ void scat2K(const int* __restrict__ e0, const int* __restrict__ e1,
                       const int* __restrict__ e2) {
    int br = blockIdx.y;
    const int* ei = br == 0 ? e0 : (br == 1 ? e1 : e2);
    int base = blockIdx.x * 1024 + threadIdx.x * 4;
    int4 s4 = __ldg((const int4*)(ei + base));
    int4 d4 = __ldg((const int4*)(ei + NE + base));
    float v0 = __ldg(&g_z2[br][s4.x]);
    float v1 = __ldg(&g_z2[br][s4.y]);
    float v2 = __ldg(&g_z2[br][s4.z]);
    float v3 = __ldg(&g_z2[br][s4.w]);
    atomicAdd(&g_acc2[br][d4.x], v0);
    atomicAdd(&g_acc2[br][d4.y], v1);
    atomicAdd(&g_acc2[br][d4.z], v2);
    atomicAdd(&g_acc2[br][d4.w], v3);
}

// ff1 tiled GEMM with fused conv2 epilogue in the A-tile load.
// grid (8 row-tiles, 5 k-splits); block 256; C tile 64x64; partials atomicAdd.
__global__ void ff1K(const float* __restrict__ b2, const float* __restrict__ w1f) {
    __shared__ float As[KT][65];   // As[kk][r] = concat value (epilogue applied)
    __shared__ float Bs[KT][64];   // Bs[kk][c] = w1f[k0+kk][c]
    int b0 = blockIdx.x * 64;
    int kbase = blockIdx.y * 600;  // 5 splits * 600 = 3000
    float b2v = __ldg(b2);
    int tid = threadIdx.x;
    int tr = tid >> 4;             // 0..15, rows tr + 16*i
    int tc = tid & 15;             // 0..15, cols tc + 16*j
    float C[4][4];
#pragma unroll
    for (int i = 0; i < 4; i++)
#pragma unroll
        for (int j = 0; j < 4; j++) C[i][j] = 0.f;

    for (int t = 0; t < 600 / KT; t++) {
        int k0 = kbase + t * KT;
        int br = k0 / NS;                 // whole tile in one branch (KT | NS alignment)
        int s0 = k0 - br * NS;
        // A tile: 64 rows x KT cols via float4 gathers (s0 % 4 == 0)
        for (int e = tid; e < (KT / 4) * 64; e += TB) {
            int kk4 = (e >> 6) << 2;      // 0,4,...,KT-4
            int r   = e & 63;
            int n   = (b0 + r) * NS + s0 + kk4;
            float4 av = *(const float4*)&g_acc2[br][n];
            uint4  dv = *(const uint4*)&g_deg[br][n];
            As[kk4 + 0][r] = fmaxf(fmaf(rsqrtf((float)(dv.x + 1u)), av.x, b2v), 0.f);
            As[kk4 + 1][r] = fmaxf(fmaf(rsqrtf((float)(dv.y + 1u)), av.y, b2v), 0.f);
            As[kk4 + 2][r] = fmaxf(fmaf(rsqrtf((float)(dv.z + 1u)), av.z, b2v), 0.f);
            As[kk4 + 3][r] = fmaxf(fmaf(rsqrtf((float)(dv.w + 1u)), av.w, b2v), 0.f);
        }
        // B tile: KT rows x 64 cols, float4 coalesced
        for (int e = tid; e < KT * 16; e += TB) {
            int kk = e >> 4;
            int c4 = (e & 15) * 4;
            float4 wv = __ldg((const float4*)(w1f + (size_t)(k0 + kk) * NH + c4));
            Bs[kk][c4 + 0] = wv.x;
            Bs[kk][c4 + 1] = wv.y;
            Bs[kk][c4 + 2] = wv.z;
            Bs[kk][c4 + 3] = wv.w;
        }
        __syncthreads();
#pragma unroll 8
        for (int kk = 0; kk < KT; kk++) {
            float a[4], b[4];
#pragma unroll
            for (int i = 0; i < 4; i++) a[i] = As[kk][tr + 16 * i];
#pragma unroll
            for (int j = 0; j < 4; j++) b[j] = Bs[kk][tc + 16 * j];
#pragma unroll
            for (int i = 0; i < 4; i++)
#pragma unroll
                for (int j = 0; j < 4; j++) C[i][j] += a[i] * b[j];
        }
        __syncthreads();
    }
#pragma unroll
    for (int i = 0; i < 4; i++)
#pragma unroll
        for (int j = 0; j < 4; j++)
            atomicAdd(&g_hidpart[(b0 + tr + 16 * i) * NH + tc + 16 * j], C[i][j]);
}

// ff2 tiled GEMM: hidden(relu(part+b1f)) @ wf2 + b2f, * mask.
// grid (8 row-tiles, 16 col-tiles); block 256; C tile 64x64.
__global__ void ff2K(const float* __restrict__ b1f, const float* __restrict__ w2f,
                     const float* __restrict__ b2f, const float* __restrict__ mask,
                     float* __restrict__ out) {
    __shared__ float As2[NH][65];  // As2[k][r] = relu(hidpart[r0+r][k] + b1f[k])
    __shared__ float Bs2[NH][64];  // Bs2[k][c] = w2f[k][c0+c]
    int r0 = blockIdx.x * 64;
    int c0 = blockIdx.y * 64;
    int tid = threadIdx.x;
    for (int e = tid; e < NH * 64; e += TB) {
        int k = e >> 6;
        int r = e & 63;
        As2[k][r] = fmaxf(g_hidpart[(r0 + r) * NH + k] + __ldg(b1f + k), 0.f);
    }
    for (int e = tid; e < NH * 16; e += TB) {
        int k  = e >> 4;
        int c4 = (e & 15) * 4;
        float4 wv = __ldg((const float4*)(w2f + (size_t)k * NA + c0 + c4));
        Bs2[k][c4 + 0] = wv.x;
        Bs2[k][c4 + 1] = wv.y;
        Bs2[k][c4 + 2] = wv.z;
        Bs2[k][c4 + 3] = wv.w;
    }
    __syncthreads();
    int tr = tid >> 4;
    int tc = tid & 15;
    float C[4][4];
#pragma unroll
    for (int i = 0; i < 4; i++)
#pragma unroll
        for (int j = 0; j < 4; j++) C[i][j] = 0.f;
#pragma unroll 8
    for (int k = 0; k < NH; k++) {
        float a[4], b[4];
#pragma unroll
        for (int i = 0; i < 4; i++) a[i] = As2[k][tr + 16 * i];
#pragma unroll
        for (int j = 0; j < 4; j++) b[j] = Bs2[k][tc + 16 * j];
#pragma unroll
        for (int i = 0; i < 4; i++)
#pragma unroll
            for (int j = 0; j < 4; j++) C[i][j] += a[i] * b[j];
    }
#pragma unroll
    for (int i = 0; i < 4; i++) {
        int b = r0 + tr + 16 * i;
#pragma unroll
        for (int j = 0; j < 4; j++) {
            int o = c0 + tc + 16 * j;
            size_t idx = (size_t)b * NA + o;
            out[idx] = (C[i][j] + __ldg(b2f + o)) * __ldg(mask + idx);
        }
    }
}

// ---------------- launch ------------------------------------------------------

extern "C" void kernel_launch(void* const* d_in, const int* in_sizes, int n_in,
                              void* d_out, int out_size) {
    const float* x0 = (const float*)d_in[0];
    const float* x1 = (const float*)d_in[1];
    const float* x2 = (const float*)d_in[2];
    const int* e0 = (const int*)d_in[3];
    const int* e1 = (const int*)d_in[4];
    const int* e2 = (const int*)d_in[5];
    const float* mask = (const float*)d_in[6];
    const float* nw  = (const float*)d_in[7];
    const float* nb  = (const float*)d_in[8];
    const float* nms = (const float*)d_in[9];
    const float* W1  = (const float*)d_in[10];
    const float* b1  = (const float*)d_in[11];
    const float* W2  = (const float*)d_in[12];
    const float* b2  = (const float*)d_in[13];
    const float* wf1 = (const float*)d_in[14];
    const float* bf1 = (const float*)d_in[15];
    const float* wf2 = (const float*)d_in[16];
    const float* bf2 = (const float*)d_in[17];
    float* out = (float*)d_out;

    dim3 gridSD(STATS_BLKS + EDGE_BLKS, 3);
    dim3 gridE(EDGE_BLKS, 3);
    dim3 gridN((NN + TB - 1) / TB, 3);

    zeroK<<<(3 * NN + TB - 1) / TB, TB>>>();
    statsdegK<<<gridSD, TB>>>(x0, x1, x2, e0, e1, e2);
    z1K<<<gridN, TB>>>(x0, x1, x2, nw, nb, nms, W1);
    scat1K<<<gridE, TB>>>(e0, e1, e2);
    h1z2K<<<gridN, TB>>>(b1, W2);
    scat2K<<<gridE, TB>>>(e0, e1, e2);
    ff1K<<<dim3(8, 5), TB>>>(b2, wf1);
    ff2K<<<dim3(8, 16), TB>>>(bf1, wf2, bf2, mask, out);
}